// round 1
// baseline (speedup 1.0000x reference)
#include <cuda_runtime.h>
#include <math.h>

#define DIM   4096
#define CAP   8192
#define TOPK  8

// Scratch (no allocations allowed in kernel_launch).
__device__ float g_weighted[CAP];
__device__ int   g_topidx[TOPK];
__device__ float g_retrieved[DIM];

// ---------------------------------------------------------------------------
// Kernel 1: fused score pass. One block per memory row.
// weighted[row] = (dot(m,q)/max(||q||*||m||, eps)) * imp[row] * exp(-0.001*age)
// Reads memory_bank exactly once (128 MiB) — DRAM-bound.
// ---------------------------------------------------------------------------
__global__ __launch_bounds__(256) void score_kernel(
    const float* __restrict__ q,
    const float* __restrict__ mb,
    const float* __restrict__ imp,
    const float* __restrict__ age)
{
    const int row = blockIdx.x;
    const float4* m  = reinterpret_cast<const float4*>(mb) + (size_t)row * (DIM / 4);
    const float4* qv = reinterpret_cast<const float4*>(q);

    float dot = 0.f, mn2 = 0.f, qn2 = 0.f;
    #pragma unroll 4
    for (int i = threadIdx.x; i < DIM / 4; i += 256) {
        float4 a = m[i];
        float4 b = qv[i];
        dot += a.x * b.x + a.y * b.y + a.z * b.z + a.w * b.w;
        mn2 += a.x * a.x + a.y * a.y + a.z * a.z + a.w * a.w;
        qn2 += b.x * b.x + b.y * b.y + b.z * b.z + b.w * b.w;
    }

    // warp reduce
    #pragma unroll
    for (int o = 16; o > 0; o >>= 1) {
        dot += __shfl_down_sync(0xffffffffu, dot, o);
        mn2 += __shfl_down_sync(0xffffffffu, mn2, o);
        qn2 += __shfl_down_sync(0xffffffffu, qn2, o);
    }

    __shared__ float s0[8], s1[8], s2[8];
    const int w = threadIdx.x >> 5;
    if ((threadIdx.x & 31) == 0) { s0[w] = dot; s1[w] = mn2; s2[w] = qn2; }
    __syncthreads();

    if (threadIdx.x == 0) {
        float d = 0.f, m2 = 0.f, q2 = 0.f;
        #pragma unroll
        for (int i = 0; i < 8; i++) { d += s0[i]; m2 += s1[i]; q2 += s2[i]; }
        float sim = d / fmaxf(sqrtf(q2) * sqrtf(m2), 1e-8f);
        g_weighted[row] = sim * imp[row] * expf(-0.001f * age[row]);
    }
}

// ---------------------------------------------------------------------------
// Kernel 2: top-8 of 8192 scores. Single block, shared-memory iterative argmax.
// ---------------------------------------------------------------------------
__global__ __launch_bounds__(1024) void topk_kernel()
{
    __shared__ float w[CAP];          // 32 KB
    __shared__ float bv[32];
    __shared__ int   bi[32];

    const int tid = threadIdx.x;
    for (int i = tid; i < CAP; i += 1024) w[i] = g_weighted[i];
    __syncthreads();

    for (int k = 0; k < TOPK; k++) {
        float best = -3.0e38f;
        int   idx  = -1;
        #pragma unroll
        for (int i = tid; i < CAP; i += 1024) {
            float v = w[i];
            if (v > best) { best = v; idx = i; }
        }
        // warp reduce (val, idx)
        #pragma unroll
        for (int o = 16; o > 0; o >>= 1) {
            float ov = __shfl_down_sync(0xffffffffu, best, o);
            int   oi = __shfl_down_sync(0xffffffffu, idx, o);
            if (ov > best) { best = ov; idx = oi; }
        }
        if ((tid & 31) == 0) { bv[tid >> 5] = best; bi[tid >> 5] = idx; }
        __syncthreads();
        if (tid == 0) {
            float bb = bv[0]; int ii = bi[0];
            #pragma unroll
            for (int j = 1; j < 32; j++)
                if (bv[j] > bb) { bb = bv[j]; ii = bi[j]; }
            g_topidx[k] = ii;
            w[ii] = -3.0e38f;   // exclude from next pass
        }
        __syncthreads();
    }
}

// ---------------------------------------------------------------------------
// Kernel 3: retrieved = mean of the 8 selected rows. 1024 float4 lanes.
// ---------------------------------------------------------------------------
__global__ __launch_bounds__(256) void gather_kernel(const float* __restrict__ mb)
{
    const int j = blockIdx.x * 256 + threadIdx.x;   // 0..1023 (float4 index)
    const float4* m = reinterpret_cast<const float4*>(mb);

    float4 acc = make_float4(0.f, 0.f, 0.f, 0.f);
    #pragma unroll
    for (int t = 0; t < TOPK; t++) {
        float4 v = m[(size_t)g_topidx[t] * (DIM / 4) + j];
        acc.x += v.x; acc.y += v.y; acc.z += v.z; acc.w += v.w;
    }
    const float inv = 1.0f / TOPK;
    reinterpret_cast<float4*>(g_retrieved)[j] =
        make_float4(acc.x * inv, acc.y * inv, acc.z * inv, acc.w * inv);
}

// ---------------------------------------------------------------------------
// Kernel 4: decode GEMV. out[i] = dot(W_dec[i,:], retrieved) + b_dec[i].
// One block per output row; W_dec read once (64 MiB) — DRAM-bound.
// ---------------------------------------------------------------------------
__global__ __launch_bounds__(256) void gemv_kernel(
    const float* __restrict__ W,
    const float* __restrict__ b,
    float* __restrict__ out)
{
    const int row = blockIdx.x;
    const float4* wr = reinterpret_cast<const float4*>(W) + (size_t)row * (DIM / 4);
    const float4* rv = reinterpret_cast<const float4*>(g_retrieved);

    float acc = 0.f;
    #pragma unroll 4
    for (int i = threadIdx.x; i < DIM / 4; i += 256) {
        float4 a = wr[i];
        float4 v = rv[i];
        acc += a.x * v.x + a.y * v.y + a.z * v.z + a.w * v.w;
    }
    #pragma unroll
    for (int o = 16; o > 0; o >>= 1)
        acc += __shfl_down_sync(0xffffffffu, acc, o);

    __shared__ float s[8];
    const int w = threadIdx.x >> 5;
    if ((threadIdx.x & 31) == 0) s[w] = acc;
    __syncthreads();
    if (threadIdx.x == 0) {
        float t = 0.f;
        #pragma unroll
        for (int i = 0; i < 8; i++) t += s[i];
        out[row] = t + b[row];
    }
}

// ---------------------------------------------------------------------------
extern "C" void kernel_launch(void* const* d_in, const int* in_sizes, int n_in,
                              void* d_out, int out_size)
{
    const float* q   = (const float*)d_in[0];  // [4096]
    const float* mb  = (const float*)d_in[1];  // [8192, 4096]
    const float* imp = (const float*)d_in[2];  // [8192]
    const float* age = (const float*)d_in[3];  // [8192]
    const float* W   = (const float*)d_in[4];  // [4096, 4096]
    const float* b   = (const float*)d_in[5];  // [4096]
    float* out = (float*)d_out;                // [4096]

    score_kernel<<<CAP, 256>>>(q, mb, imp, age);
    topk_kernel<<<1, 1024>>>();
    gather_kernel<<<DIM / 4 / 256, 256>>>(mb);
    gemv_kernel<<<DIM, 256>>>(W, b, out);
}